// round 5
// baseline (speedup 1.0000x reference)
#include <cuda_runtime.h>
#include <math_constants.h>

#define N_BOX 1024
#define P_PTS 4096
#define NTHREADS 256
#define NWARPS (NTHREADS / 32)
#define SPLIT 4
#define NBLOCKS (N_BOX * SPLIT)              /* 4096 */
#define PTS_PER_BLK (P_PTS / SPLIT)          /* 1024 */
#define VEC_PER_BLK (PTS_PER_BLK / 2)        /* 512 */
#define ITERS (VEC_PER_BLK / NTHREADS)       /* 2 */

#define PI_F      3.14159274101257324219f
#define HALF_PI_F 1.57079637050628662109f

__device__ float g_psum[NBLOCKS];
__device__ int   g_pcnt[NBLOCKS];
__device__ int   g_count;   // zero-init at load; reset by last block each launch

__device__ __forceinline__ float frcp_approx(float x) {
    float r;
    asm("rcp.approx.f32 %0, %1;" : "=f"(r) : "f"(x));
    return r;
}

// slot layout: pair02 = slots {0,1} (preferred first), pair13 = slots {2,3}
struct BoxConsts {
    float k1, k2;
    float bsA, bsB;   // pair02: |bsA| <= |bsB| (tie keeps original edge order)
    float bsC, bsD;   // pair13
    float MX[4], WX[4];
    float MY[4], WY[4];
};

__device__ __forceinline__ void make_interval(float lo, float hi, float bs,
                                              float& MID, float& HW)
{
    if (lo >= hi) {                 // empty interval (degenerate edge)
        MID = 0.0f; HW = -1.0f;
    } else if (bs == 0.0f) {        // ix == 0 always: inside iff 0 in (lo,hi)
        MID = 0.0f;
        HW = (lo < 0.0f && 0.0f < hi) ? CUDART_INF_F : -1.0f;
    } else {
        const float a = __fdividef(lo, bs);
        const float b = __fdividef(hi, bs);
        const float A = fminf(a, b), B = fmaxf(a, b);
        MID = 0.5f * (A + B);
        HW  = 0.5f * (B - A);
    }
}

__global__ __launch_bounds__(NTHREADS, 6)
void wdm3d_fused_kernel(const float*  __restrict__ wl,
                        const float*  __restrict__ Ry,
                        const float4* __restrict__ points4,
                        const float2* __restrict__ density2,
                        const float*  __restrict__ center,
                        float* __restrict__ out)
{
    const int blk  = blockIdx.x;
    const int n    = blk >> 2;        // box index
    const int part = blk & 3;         // quarter of the point set
    __shared__ BoxConsts C;

    const unsigned full = 0xFFFFFFFFu;

    // ---------------- per-box constants: warp 0 (sincos parallel over 4 lanes)
    if (threadIdx.x < 32) {
        const int lane = threadIdx.x;
        const float w  = wl[2 * n];
        const float l  = wl[2 * n + 1];
        const float ry = Ry[n];
        const float ccx = center[2 * n];
        const float ccy = center[2 * n + 1];

        const float init_theta = atanf(w / l);
        const float len = sqrtf(w * w + l * l) * 0.5f;

        const int j = lane & 3;
        float ang = init_theta + ry;
        if (j == 1) ang = (PI_F - init_theta) + ry;
        if (j == 2) ang = (PI_F + init_theta) + ry;
        if (j == 3) ang = (-init_theta) + ry;
        float sj, cj;
        sincosf(ang, &sj, &cj);
        const float cxl = len * cj + ccx;
        const float cyl = len * sj + ccy;

        const float cx0 = __shfl_sync(full, cxl, 0), cy0 = __shfl_sync(full, cyl, 0);
        const float cx1 = __shfl_sync(full, cxl, 1), cy1 = __shfl_sync(full, cyl, 1);
        const float cx2 = __shfl_sync(full, cxl, 2), cy2 = __shfl_sync(full, cyl, 2);
        const float cx3 = __shfl_sync(full, cxl, 3), cy3 = __shfl_sync(full, cyl, 3);

        float ry2 = (ry == HALF_PI_F) ? (ry - 0.0001f) : ry;
        ry2 = (ry2 == 0.0f) ? (ry2 + 0.0001f) : ry2;
        const float k1 = tanf(ry2);
        const float k2 = tanf(ry2 + HALF_PI_F);

        float bs[4];
        bs[0] = cy0 - k1 * cx0;   // b11
        bs[1] = cy2 - k2 * cx2;   // b22
        bs[2] = cy2 - k1 * cx2;   // b12
        bs[3] = cy0 - k2 * cx0;   // b21

        const float cxr[4] = { rintf(cx0 * 1e4f), rintf(cx1 * 1e4f),
                               rintf(cx2 * 1e4f), rintf(cx3 * 1e4f) };
        const float cyr[4] = { rintf(cy0 * 1e4f), rintf(cy1 * 1e4f),
                               rintf(cy2 * 1e4f), rintf(cy3 * 1e4f) };

        float MX[4], WX[4], MY[4], WY[4];
        const float S = 1e-4f;
#pragma unroll
        for (int e = 0; e < 4; e++) {
            const int e2 = (e + 1) & 3;
            const float lox = (fminf(cxr[e], cxr[e2]) + 0.5f) * S;
            const float hix = (fmaxf(cxr[e], cxr[e2]) - 0.5f) * S;
            const float loy = (fminf(cyr[e], cyr[e2]) + 0.5f) * S;
            const float hiy = (fmaxf(cyr[e], cyr[e2]) - 0.5f) * S;
            make_interval(lox, hix, bs[e], MX[e], WX[e]);
            make_interval(loy, hiy, bs[e], MY[e], WY[e]);
        }

        int p0 = 0, p2 = 2;
        if (fabsf(bs[2]) < fabsf(bs[0])) { p0 = 2; p2 = 0; }
        int p1 = 1, p3 = 3;
        if (fabsf(bs[3]) < fabsf(bs[1])) { p1 = 3; p3 = 1; }

        if (lane == 0) {
            C.k1 = k1; C.k2 = k2;
            C.bsA = bs[p0]; C.bsB = bs[p2];
            C.bsC = bs[p1]; C.bsD = bs[p3];
            C.MX[0] = MX[p0]; C.WX[0] = WX[p0]; C.MY[0] = MY[p0]; C.WY[0] = WY[p0];
            C.MX[1] = MX[p2]; C.WX[1] = WX[p2]; C.MY[1] = MY[p2]; C.WY[1] = WY[p2];
            C.MX[2] = MX[p1]; C.WX[2] = WX[p1]; C.MY[2] = MY[p1]; C.WY[2] = WY[p1];
            C.MX[3] = MX[p3]; C.WX[3] = WX[p3]; C.MY[3] = MY[p3]; C.WY[3] = WY[p3];
        }
    }
    __syncthreads();

    const float k1 = C.k1, k2 = C.k2;
    const float bsA = C.bsA, bsB = C.bsB, bsC = C.bsC, bsD = C.bsD;
    const float MX0 = C.MX[0], WX0 = C.WX[0], MY0 = C.MY[0], WY0 = C.WY[0];
    const float MX1 = C.MX[1], WX1 = C.WX[1], MY1 = C.MY[1], WY1 = C.WY[1];
    const float MX2 = C.MX[2], WX2 = C.WX[2], MY2 = C.MY[2], WY2 = C.WY[2];
    const float MX3 = C.MX[3], WX3 = C.WX[3], MY3 = C.MY[3], WY3 = C.WY[3];

    const size_t base = (size_t)n * (P_PTS / 2) + (size_t)part * VEC_PER_BLK;
    const float4* __restrict__ pts = points4  + base;
    const float2* __restrict__ den = density2 + base;

    float sum = 0.0f;
    int   cnt = 0;

#define PROCESS_POINT(PX_, PY_, DENS_)                                          \
    do {                                                                        \
        const float px = ((PX_) == 0.0f) ? 0.0001f : (PX_);                     \
        const float py = (PY_);                                                 \
        const float r1 = frcp_approx(fmaf(-k1, px, py));                        \
        const float r2 = frcp_approx(fmaf(-k2, px, py));                        \
        const float u1 = px * r1, v1 = py * r1;                                 \
        const float u2 = px * r2, v2 = py * r2;                                 \
        const bool mA = (fabsf(u1 - MX0) < WX0) || (fabsf(v1 - MY0) < WY0);     \
        const bool mB = (fabsf(u1 - MX1) < WX1) || (fabsf(v1 - MY1) < WY1);     \
        const bool mC = (fabsf(u2 - MX2) < WX2) || (fabsf(v2 - MY2) < WY2);     \
        const bool mD = (fabsf(u2 - MX3) < WX3) || (fabsf(v2 - MY3) < WY3);     \
        const int pc = (int)mA + (int)mB + (int)mC + (int)mD;                   \
        /* g = bs*r; cen ∝ |px|*|g| so argmin compares |g| (shared |px|>0);  */ \
        /* dis = |ix-px|+|iy-py| = (|px|+|py|) * |g-1|                       */ \
        const float g02 = (mA ? bsA : bsB) * r1;                                \
        const float g13 = (mC ? bsC : bsD) * r2;                                \
        const float c02 = (mA || mB) ? fabsf(g02) : CUDART_INF_F;               \
        const float c13 = (mC || mD) ? fabsf(g13) : CUDART_INF_F;               \
        const float gw  = (c02 <= c13) ? g02 : g13;                             \
        if (pc == 2) {                                                          \
            const float dsel = (fabsf(px) + fabsf(py)) * fabsf(gw - 1.0f);      \
            sum += dsel * frcp_approx(DENS_);                                   \
            cnt += 1;                                                           \
        }                                                                       \
    } while (0)

    float4 p[ITERS];
    float2 d[ITERS];
#pragma unroll
    for (int it = 0; it < ITERS; it++) {
        p[it] = pts[threadIdx.x + it * NTHREADS];
        d[it] = den[threadIdx.x + it * NTHREADS];
    }
#pragma unroll
    for (int it = 0; it < ITERS; it++) {
        PROCESS_POINT(p[it].x, p[it].y, d[it].x);
        PROCESS_POINT(p[it].z, p[it].w, d[it].y);
    }

    // ---------------- block reduction
#pragma unroll
    for (int off = 16; off > 0; off >>= 1) {
        sum += __shfl_down_sync(full, sum, off);
        cnt += __shfl_down_sync(full, cnt, off);
    }

    __shared__ float s_sum[NWARPS];
    __shared__ int   s_cnt[NWARPS];
    __shared__ bool  s_last;
    const int warp = threadIdx.x >> 5;
    const int lane = threadIdx.x & 31;
    if (lane == 0) { s_sum[warp] = sum; s_cnt[warp] = cnt; }
    __syncthreads();

    if (threadIdx.x == 0) {
        float fs = 0.0f; int fc = 0;
#pragma unroll
        for (int wi = 0; wi < NWARPS; wi++) { fs += s_sum[wi]; fc += s_cnt[wi]; }
        g_psum[blk] = fs;
        g_pcnt[blk] = fc;
        __threadfence();
        const int prev = atomicAdd(&g_count, 1);
        s_last = (prev == gridDim.x - 1);
    }
    __syncthreads();

    // ---------------- last block: deterministic final reduction over boxes
    if (s_last) {
        float fs = 0.0f;
        int   fv = 0;
#pragma unroll
        for (int jb = 0; jb < N_BOX / NTHREADS; jb++) {
            const int b = threadIdx.x + jb * NTHREADS;
            float bsum = 0.0f; int bcnt = 0;
#pragma unroll
            for (int q = 0; q < SPLIT; q++) {
                bsum += __ldcg(&g_psum[SPLIT * b + q]);
                bcnt += __ldcg(&g_pcnt[SPLIT * b + q]);
            }
            const bool valid = (bcnt >= 3);
            fs += valid ? (bsum / (float)max(bcnt, 1)) : 0.0f;
            fv += valid ? 1 : 0;
        }
#pragma unroll
        for (int off = 16; off > 0; off >>= 1) {
            fs += __shfl_down_sync(full, fs, off);
            fv += __shfl_down_sync(full, fv, off);
        }
        __shared__ float f_sum[NWARPS];
        __shared__ int   f_cnt[NWARPS];
        if (lane == 0) { f_sum[warp] = fs; f_cnt[warp] = fv; }
        __syncthreads();
        if (threadIdx.x == 0) {
            float ts = 0.0f; int tv = 0;
#pragma unroll
            for (int wi = 0; wi < NWARPS; wi++) { ts += f_sum[wi]; tv += f_cnt[wi]; }
            out[0] = ts / (float)max(tv, 1);
            g_count = 0;
        }
    }
}

extern "C" void kernel_launch(void* const* d_in, const int* in_sizes, int n_in,
                              void* d_out, int out_size)
{
    const float*  wl       = (const float*)d_in[0];
    const float*  Ry       = (const float*)d_in[1];
    const float4* points4  = (const float4*)d_in[2];
    const float2* density2 = (const float2*)d_in[3];
    const float*  center   = (const float*)d_in[4];
    float* out = (float*)d_out;

    wdm3d_fused_kernel<<<NBLOCKS, NTHREADS>>>(wl, Ry, points4, density2, center, out);
}

// round 6
// speedup vs baseline: 1.0569x; 1.0569x over previous
#include <cuda_runtime.h>
#include <math_constants.h>

#define N_BOX 1024
#define P_PTS 4096
#define NTHREADS 256
#define NWARPS (NTHREADS / 32)
#define SPLIT 4
#define NBLOCKS (N_BOX * SPLIT)              /* 4096 */
#define PTS_PER_BLK (P_PTS / SPLIT)          /* 1024 */
#define VEC_PER_BLK (PTS_PER_BLK / 2)        /* 512 */
#define ITERS (VEC_PER_BLK / NTHREADS)       /* 2 */

#define PI_F      3.14159274101257324219f
#define HALF_PI_F 1.57079637050628662109f

__device__ float g_psum[NBLOCKS];
__device__ int   g_pcnt[NBLOCKS];
__device__ int   g_count;   // zero-init at load; reset by last block each launch

__device__ __forceinline__ float frcp_approx(float x) {
    float r;
    asm("rcp.approx.f32 %0, %1;" : "=f"(r) : "f"(x));
    return r;
}

// slot layout: pair02 = slots {0,1} (preferred first), pair13 = slots {2,3}
struct BoxConsts {
    float k1, k2;
    float bsA, bsB;   // pair02: |bsA| <= |bsB| (tie keeps original edge order)
    float bsC, bsD;   // pair13
    float MX[4], WX[4];
    float MY[4], WY[4];
};

__device__ __forceinline__ void make_interval(float lo, float hi, float bs,
                                              float& MID, float& HW)
{
    if (lo >= hi) {                 // empty interval (degenerate edge)
        MID = 0.0f; HW = -1.0f;
    } else if (bs == 0.0f) {        // ix == 0 always: inside iff 0 in (lo,hi)
        MID = 0.0f;
        HW = (lo < 0.0f && 0.0f < hi) ? CUDART_INF_F : -1.0f;
    } else {
        const float a = __fdividef(lo, bs);
        const float b = __fdividef(hi, bs);
        const float A = fminf(a, b), B = fmaxf(a, b);
        MID = 0.5f * (A + B);
        HW  = 0.5f * (B - A);
    }
}

__global__ __launch_bounds__(NTHREADS, 6)
void wdm3d_fused_kernel(const float*  __restrict__ wl,
                        const float*  __restrict__ Ry,
                        const float4* __restrict__ points4,
                        const float2* __restrict__ density2,
                        const float*  __restrict__ center,
                        float* __restrict__ out)
{
    const int blk  = blockIdx.x;
    const int n    = blk >> 2;        // box index
    const int part = blk & 3;         // quarter of the point set
    __shared__ BoxConsts C;

    const unsigned full = 0xFFFFFFFFu;

    // ---------------- issue point loads FIRST: DRAM latency overlaps preamble
    const size_t base = (size_t)n * (P_PTS / 2) + (size_t)part * VEC_PER_BLK;
    const float4* __restrict__ pts = points4  + base;
    const float2* __restrict__ den = density2 + base;

    float4 p[ITERS];
    float2 d[ITERS];
#pragma unroll
    for (int it = 0; it < ITERS; it++) {
        p[it] = pts[threadIdx.x + it * NTHREADS];
        d[it] = den[threadIdx.x + it * NTHREADS];
    }

    // ---------------- per-box constants: thread 0, trig-identity slim form
    if (threadIdx.x == 0) {
        const float w  = wl[2 * n];
        const float l  = wl[2 * n + 1];
        const float ry = Ry[n];
        const float ccx = center[2 * n];
        const float ccy = center[2 * n + 1];

        // init_theta = atan(w/l); len = hypot(w,l)/2.
        // len*cos(init_theta±ry) etc. collapse to linear forms in (w,l,sincos(ry)):
        float sr, cr;
        sincosf(ry, &sr, &cr);
        const float P  = 0.5f * (l * cr - w * sr);   // len*cos(it+ry)
        const float Q  = 0.5f * (w * cr + l * sr);   // len*sin(it+ry)
        const float R  = 0.5f * (l * cr + w * sr);   // len*cos(it-ry)
        const float S_ = 0.5f * (w * cr - l * sr);   // len*sin(it-ry)

        const float cx0 = ccx + P,  cy0 = ccy + Q;   // ang = it+ry
        const float cx1 = ccx - R,  cy1 = ccy + S_;  // ang = pi-it+ry
        const float cx2 = ccx - P,  cy2 = ccy - Q;   // ang = pi+it+ry
        const float cx3 = ccx + R,  cy3 = ccy - S_;  // ang = -it+ry

        float ry2 = (ry == HALF_PI_F) ? (ry - 0.0001f) : ry;
        ry2 = (ry2 == 0.0f) ? (ry2 + 0.0001f) : ry2;
        float sr2 = sr, cr2 = cr;
        if (ry2 != ry) sincosf(ry2, &sr2, &cr2);
        const float k1 =  __fdividef(sr2, cr2);      // tan(ry2)
        const float k2 = -__fdividef(cr2, sr2);      // tan(ry2+pi/2) = -cot(ry2)

        float bs[4];
        bs[0] = cy0 - k1 * cx0;   // b11
        bs[1] = cy2 - k2 * cx2;   // b22
        bs[2] = cy2 - k1 * cx2;   // b12
        bs[3] = cy0 - k2 * cx0;   // b21

        const float cxr[4] = { rintf(cx0 * 1e4f), rintf(cx1 * 1e4f),
                               rintf(cx2 * 1e4f), rintf(cx3 * 1e4f) };
        const float cyr[4] = { rintf(cy0 * 1e4f), rintf(cy1 * 1e4f),
                               rintf(cy2 * 1e4f), rintf(cy3 * 1e4f) };

        float MX[4], WX[4], MY[4], WY[4];
        const float S = 1e-4f;
#pragma unroll
        for (int e = 0; e < 4; e++) {
            const int e2 = (e + 1) & 3;
            const float lox = (fminf(cxr[e], cxr[e2]) + 0.5f) * S;
            const float hix = (fmaxf(cxr[e], cxr[e2]) - 0.5f) * S;
            const float loy = (fminf(cyr[e], cyr[e2]) + 0.5f) * S;
            const float hiy = (fmaxf(cyr[e], cyr[e2]) - 0.5f) * S;
            make_interval(lox, hix, bs[e], MX[e], WX[e]);
            make_interval(loy, hiy, bs[e], MY[e], WY[e]);
        }

        int p0 = 0, p2 = 2;
        if (fabsf(bs[2]) < fabsf(bs[0])) { p0 = 2; p2 = 0; }
        int p1 = 1, p3 = 3;
        if (fabsf(bs[3]) < fabsf(bs[1])) { p1 = 3; p3 = 1; }

        C.k1 = k1; C.k2 = k2;
        C.bsA = bs[p0]; C.bsB = bs[p2];
        C.bsC = bs[p1]; C.bsD = bs[p3];
        C.MX[0] = MX[p0]; C.WX[0] = WX[p0]; C.MY[0] = MY[p0]; C.WY[0] = WY[p0];
        C.MX[1] = MX[p2]; C.WX[1] = WX[p2]; C.MY[1] = MY[p2]; C.WY[1] = WY[p2];
        C.MX[2] = MX[p1]; C.WX[2] = WX[p1]; C.MY[2] = MY[p1]; C.WY[2] = WY[p1];
        C.MX[3] = MX[p3]; C.WX[3] = WX[p3]; C.MY[3] = MY[p3]; C.WY[3] = WY[p3];
    }
    __syncthreads();

    const float k1 = C.k1, k2 = C.k2;
    const float bsA = C.bsA, bsB = C.bsB, bsC = C.bsC, bsD = C.bsD;
    const float MX0 = C.MX[0], WX0 = C.WX[0], MY0 = C.MY[0], WY0 = C.WY[0];
    const float MX1 = C.MX[1], WX1 = C.WX[1], MY1 = C.MY[1], WY1 = C.WY[1];
    const float MX2 = C.MX[2], WX2 = C.WX[2], MY2 = C.MY[2], WY2 = C.WY[2];
    const float MX3 = C.MX[3], WX3 = C.WX[3], MY3 = C.MY[3], WY3 = C.WY[3];

    float sum = 0.0f;
    int   cnt = 0;

#define PROCESS_POINT(PX_, PY_, DENS_)                                          \
    do {                                                                        \
        const float px = ((PX_) == 0.0f) ? 0.0001f : (PX_);                     \
        const float py = (PY_);                                                 \
        const float r1 = frcp_approx(fmaf(-k1, px, py));                        \
        const float r2 = frcp_approx(fmaf(-k2, px, py));                        \
        const float u1 = px * r1, v1 = py * r1;                                 \
        const float u2 = px * r2, v2 = py * r2;                                 \
        const bool mA = (fabsf(u1 - MX0) < WX0) || (fabsf(v1 - MY0) < WY0);     \
        const bool mB = (fabsf(u1 - MX1) < WX1) || (fabsf(v1 - MY1) < WY1);     \
        const bool mC = (fabsf(u2 - MX2) < WX2) || (fabsf(v2 - MY2) < WY2);     \
        const bool mD = (fabsf(u2 - MX3) < WX3) || (fabsf(v2 - MY3) < WY3);     \
        const int pc = (int)mA + (int)mB + (int)mC + (int)mD;                   \
        /* g = bs*r; cen ∝ |px|*|g| -> argmin compares |g|;                  */ \
        /* dis = (|px|+|py|)*|g-1|                                           */ \
        const float g02 = (mA ? bsA : bsB) * r1;                                \
        const float g13 = (mC ? bsC : bsD) * r2;                                \
        const float c02 = (mA || mB) ? fabsf(g02) : CUDART_INF_F;               \
        const float c13 = (mC || mD) ? fabsf(g13) : CUDART_INF_F;               \
        const float gw  = (c02 <= c13) ? g02 : g13;                             \
        if (pc == 2) {                                                          \
            const float dsel = (fabsf(px) + fabsf(py)) * fabsf(gw - 1.0f);      \
            sum += dsel * frcp_approx(DENS_);                                   \
            cnt += 1;                                                           \
        }                                                                       \
    } while (0)

#pragma unroll
    for (int it = 0; it < ITERS; it++) {
        PROCESS_POINT(p[it].x, p[it].y, d[it].x);
        PROCESS_POINT(p[it].z, p[it].w, d[it].y);
    }

    // ---------------- block reduction
#pragma unroll
    for (int off = 16; off > 0; off >>= 1) {
        sum += __shfl_down_sync(full, sum, off);
        cnt += __shfl_down_sync(full, cnt, off);
    }

    __shared__ float s_sum[NWARPS];
    __shared__ int   s_cnt[NWARPS];
    __shared__ bool  s_last;
    const int warp = threadIdx.x >> 5;
    const int lane = threadIdx.x & 31;
    if (lane == 0) { s_sum[warp] = sum; s_cnt[warp] = cnt; }
    __syncthreads();

    if (threadIdx.x == 0) {
        float fs = 0.0f; int fc = 0;
#pragma unroll
        for (int wi = 0; wi < NWARPS; wi++) { fs += s_sum[wi]; fc += s_cnt[wi]; }
        g_psum[blk] = fs;
        g_pcnt[blk] = fc;
        __threadfence();
        const int prev = atomicAdd(&g_count, 1);
        s_last = (prev == gridDim.x - 1);
    }
    __syncthreads();

    // ---------------- last block: deterministic final reduction over boxes
    if (s_last) {
        float fs = 0.0f;
        int   fv = 0;
#pragma unroll
        for (int jb = 0; jb < N_BOX / NTHREADS; jb++) {
            const int b = threadIdx.x + jb * NTHREADS;
            float bsum = 0.0f; int bcnt = 0;
#pragma unroll
            for (int q = 0; q < SPLIT; q++) {
                bsum += __ldcg(&g_psum[SPLIT * b + q]);
                bcnt += __ldcg(&g_pcnt[SPLIT * b + q]);
            }
            const bool valid = (bcnt >= 3);
            fs += valid ? (bsum / (float)max(bcnt, 1)) : 0.0f;
            fv += valid ? 1 : 0;
        }
#pragma unroll
        for (int off = 16; off > 0; off >>= 1) {
            fs += __shfl_down_sync(full, fs, off);
            fv += __shfl_down_sync(full, fv, off);
        }
        __shared__ float f_sum[NWARPS];
        __shared__ int   f_cnt[NWARPS];
        if (lane == 0) { f_sum[warp] = fs; f_cnt[warp] = fv; }
        __syncthreads();
        if (threadIdx.x == 0) {
            float ts = 0.0f; int tv = 0;
#pragma unroll
            for (int wi = 0; wi < NWARPS; wi++) { ts += f_sum[wi]; tv += f_cnt[wi]; }
            out[0] = ts / (float)max(tv, 1);
            g_count = 0;
        }
    }
}

extern "C" void kernel_launch(void* const* d_in, const int* in_sizes, int n_in,
                              void* d_out, int out_size)
{
    const float*  wl       = (const float*)d_in[0];
    const float*  Ry       = (const float*)d_in[1];
    const float4* points4  = (const float4*)d_in[2];
    const float2* density2 = (const float2*)d_in[3];
    const float*  center   = (const float*)d_in[4];
    float* out = (float*)d_out;

    wdm3d_fused_kernel<<<NBLOCKS, NTHREADS>>>(wl, Ry, points4, density2, center, out);
}

// round 8
// speedup vs baseline: 1.0677x; 1.0102x over previous
#include <cuda_runtime.h>
#include <math_constants.h>

#define N_BOX 1024
#define P_PTS 4096
#define NTHREADS 256
#define NWARPS (NTHREADS / 32)
#define SPLIT 2
#define NBLOCKS (N_BOX * SPLIT)              /* 2048 */
#define PTS_PER_BLK (P_PTS / SPLIT)          /* 2048 */
#define VEC_PER_BLK (PTS_PER_BLK / 2)        /* 1024 float4 */
#define ITERS (VEC_PER_BLK / NTHREADS)       /* 4 */

#define PI_F      3.14159274101257324219f
#define HALF_PI_F 1.57079637050628662109f

__device__ float g_psum[NBLOCKS];
__device__ int   g_pcnt[NBLOCKS];
__device__ int   g_count;   // zero-init at load; reset by last block each launch

__device__ __forceinline__ float frcp_approx(float x) {
    float r;
    asm("rcp.approx.f32 %0, %1;" : "=f"(r) : "f"(x));
    return r;
}

__device__ __forceinline__ void make_interval(float lo, float hi, float bs,
                                              float& MID, float& HW)
{
    if (lo >= hi) {                 // empty interval (degenerate edge)
        MID = 0.0f; HW = -1.0f;
    } else if (bs == 0.0f) {        // ix == 0 always: inside iff 0 in (lo,hi)
        MID = 0.0f;
        HW = (lo < 0.0f && 0.0f < hi) ? CUDART_INF_F : -1.0f;
    } else {
        const float a = __fdividef(lo, bs);
        const float b = __fdividef(hi, bs);
        const float A = fminf(a, b), B = fmaxf(a, b);
        MID = 0.5f * (A + B);
        HW  = 0.5f * (B - A);
    }
}

__global__ __launch_bounds__(NTHREADS, 4)
void wdm3d_fused_kernel(const float*  __restrict__ wl,
                        const float*  __restrict__ Ry,
                        const float4* __restrict__ points4,
                        const float2* __restrict__ density2,
                        const float*  __restrict__ center,
                        float* __restrict__ out)
{
    const int blk  = blockIdx.x;
    const int n    = blk >> 1;        // box index
    const int part = blk & 1;         // half of the point set
    const unsigned full = 0xFFFFFFFFu;

    // ---------------- issue ALL point loads first: DRAM latency overlaps preamble
    // d[it] pairs EXACTLY with p[it]: both are point-pair index tid + it*256
    const size_t basev = (size_t)n * (P_PTS / 2) + (size_t)part * VEC_PER_BLK;
    const float4* __restrict__ pts = points4  + basev;
    const float2* __restrict__ den = density2 + basev;

    float4 p[ITERS];
    float2 d[ITERS];
#pragma unroll
    for (int it = 0; it < ITERS; it++) {
        p[it] = pts[threadIdx.x + it * NTHREADS];
        d[it] = den[threadIdx.x + it * NTHREADS];
    }

    // ---------------- per-box constants: computed redundantly by EVERY thread
    // (block-uniform -> no shared mem, no barrier, warps fully independent)
    float k1, k2, bsA, bsB, bsC, bsD;
    float MX0, WX0, MY0, WY0, MX1, WX1, MY1, WY1;
    float MX2, WX2, MY2, WY2, MX3, WX3, MY3, WY3;
    {
        const float w  = __ldg(&wl[2 * n]);
        const float l  = __ldg(&wl[2 * n + 1]);
        const float ry = __ldg(&Ry[n]);
        const float ccx = __ldg(&center[2 * n]);
        const float ccy = __ldg(&center[2 * n + 1]);

        // len*cos(init_theta±ry) collapse to linear forms in (w,l,sincos(ry))
        float sr, cr;
        sincosf(ry, &sr, &cr);
        const float P  = 0.5f * (l * cr - w * sr);
        const float Q  = 0.5f * (w * cr + l * sr);
        const float R  = 0.5f * (l * cr + w * sr);
        const float S_ = 0.5f * (w * cr - l * sr);

        const float cx0 = ccx + P,  cy0 = ccy + Q;
        const float cx1 = ccx - R,  cy1 = ccy + S_;
        const float cx2 = ccx - P,  cy2 = ccy - Q;
        const float cx3 = ccx + R,  cy3 = ccy - S_;

        float ry2 = (ry == HALF_PI_F) ? (ry - 0.0001f) : ry;
        ry2 = (ry2 == 0.0f) ? (ry2 + 0.0001f) : ry2;
        float sr2 = sr, cr2 = cr;
        if (ry2 != ry) sincosf(ry2, &sr2, &cr2);
        k1 =  __fdividef(sr2, cr2);      // tan(ry2)
        k2 = -__fdividef(cr2, sr2);      // tan(ry2+pi/2)

        float bs[4];
        bs[0] = cy0 - k1 * cx0;   // b11
        bs[1] = cy2 - k2 * cx2;   // b22
        bs[2] = cy2 - k1 * cx2;   // b12
        bs[3] = cy0 - k2 * cx0;   // b21

        const float cxr[4] = { rintf(cx0 * 1e4f), rintf(cx1 * 1e4f),
                               rintf(cx2 * 1e4f), rintf(cx3 * 1e4f) };
        const float cyr[4] = { rintf(cy0 * 1e4f), rintf(cy1 * 1e4f),
                               rintf(cy2 * 1e4f), rintf(cy3 * 1e4f) };

        float MX[4], WX[4], MY[4], WY[4];
        const float S = 1e-4f;
#pragma unroll
        for (int e = 0; e < 4; e++) {
            const int e2 = (e + 1) & 3;
            const float lox = (fminf(cxr[e], cxr[e2]) + 0.5f) * S;
            const float hix = (fmaxf(cxr[e], cxr[e2]) - 0.5f) * S;
            const float loy = (fminf(cyr[e], cyr[e2]) + 0.5f) * S;
            const float hiy = (fmaxf(cyr[e], cyr[e2]) - 0.5f) * S;
            make_interval(lox, hix, bs[e], MX[e], WX[e]);
            make_interval(loy, hiy, bs[e], MY[e], WY[e]);
        }

        int p0 = 0, p2 = 2;
        if (fabsf(bs[2]) < fabsf(bs[0])) { p0 = 2; p2 = 0; }
        int p1 = 1, p3 = 3;
        if (fabsf(bs[3]) < fabsf(bs[1])) { p1 = 3; p3 = 1; }

        bsA = bs[p0]; bsB = bs[p2];
        bsC = bs[p1]; bsD = bs[p3];
        MX0 = MX[p0]; WX0 = WX[p0]; MY0 = MY[p0]; WY0 = WY[p0];
        MX1 = MX[p2]; WX1 = WX[p2]; MY1 = MY[p2]; WY1 = WY[p2];
        MX2 = MX[p1]; WX2 = WX[p1]; MY2 = MY[p1]; WY2 = WY[p1];
        MX3 = MX[p3]; WX3 = WX[p3]; MY3 = MY[p3]; WY3 = WY[p3];
    }

    float sum = 0.0f;
    int   cnt = 0;

#define PROCESS_POINT(PX_, PY_, DENS_)                                          \
    do {                                                                        \
        const float px = ((PX_) == 0.0f) ? 0.0001f : (PX_);                     \
        const float py = (PY_);                                                 \
        const float r1 = frcp_approx(fmaf(-k1, px, py));                        \
        const float r2 = frcp_approx(fmaf(-k2, px, py));                        \
        const float u1 = px * r1, v1 = py * r1;                                 \
        const float u2 = px * r2, v2 = py * r2;                                 \
        const bool mA = (fabsf(u1 - MX0) < WX0) || (fabsf(v1 - MY0) < WY0);     \
        const bool mB = (fabsf(u1 - MX1) < WX1) || (fabsf(v1 - MY1) < WY1);     \
        const bool mC = (fabsf(u2 - MX2) < WX2) || (fabsf(v2 - MY2) < WY2);     \
        const bool mD = (fabsf(u2 - MX3) < WX3) || (fabsf(v2 - MY3) < WY3);     \
        const int pc = (int)mA + (int)mB + (int)mC + (int)mD;                   \
        /* g = bs*r; cen ∝ |px|*|g| -> argmin compares |g|;                  */ \
        /* dis = (|px|+|py|)*|g-1|                                           */ \
        const float g02 = (mA ? bsA : bsB) * r1;                                \
        const float g13 = (mC ? bsC : bsD) * r2;                                \
        const float c02 = (mA || mB) ? fabsf(g02) : CUDART_INF_F;               \
        const float c13 = (mC || mD) ? fabsf(g13) : CUDART_INF_F;               \
        const float gw  = (c02 <= c13) ? g02 : g13;                             \
        if (pc == 2) {                                                          \
            const float dsel = (fabsf(px) + fabsf(py)) * fabsf(gw - 1.0f);      \
            sum += dsel * frcp_approx(DENS_);                                   \
            cnt += 1;                                                           \
        }                                                                       \
    } while (0)

#pragma unroll
    for (int it = 0; it < ITERS; it++) {
        PROCESS_POINT(p[it].x, p[it].y, d[it].x);
        PROCESS_POINT(p[it].z, p[it].w, d[it].y);
    }

    // ---------------- block reduction
#pragma unroll
    for (int off = 16; off > 0; off >>= 1) {
        sum += __shfl_down_sync(full, sum, off);
        cnt += __shfl_down_sync(full, cnt, off);
    }

    __shared__ float s_sum[NWARPS];
    __shared__ int   s_cnt[NWARPS];
    __shared__ bool  s_last;
    const int warp = threadIdx.x >> 5;
    const int lane = threadIdx.x & 31;
    if (lane == 0) { s_sum[warp] = sum; s_cnt[warp] = cnt; }
    __syncthreads();

    if (threadIdx.x == 0) {
        float fs = 0.0f; int fc = 0;
#pragma unroll
        for (int wi = 0; wi < NWARPS; wi++) { fs += s_sum[wi]; fc += s_cnt[wi]; }
        g_psum[blk] = fs;
        g_pcnt[blk] = fc;
        __threadfence();
        const int prev = atomicAdd(&g_count, 1);
        s_last = (prev == gridDim.x - 1);
    }
    __syncthreads();

    // ---------------- last block: deterministic final reduction over boxes
    if (s_last) {
        float fs = 0.0f;
        int   fv = 0;
#pragma unroll
        for (int jb = 0; jb < N_BOX / NTHREADS; jb++) {
            const int b = threadIdx.x + jb * NTHREADS;
            float bsum = 0.0f; int bcnt = 0;
#pragma unroll
            for (int q = 0; q < SPLIT; q++) {
                bsum += __ldcg(&g_psum[SPLIT * b + q]);
                bcnt += __ldcg(&g_pcnt[SPLIT * b + q]);
            }
            const bool valid = (bcnt >= 3);
            fs += valid ? (bsum / (float)max(bcnt, 1)) : 0.0f;
            fv += valid ? 1 : 0;
        }
#pragma unroll
        for (int off = 16; off > 0; off >>= 1) {
            fs += __shfl_down_sync(full, fs, off);
            fv += __shfl_down_sync(full, fv, off);
        }
        __shared__ float f_sum[NWARPS];
        __shared__ int   f_cnt[NWARPS];
        if (lane == 0) { f_sum[warp] = fs; f_cnt[warp] = fv; }
        __syncthreads();
        if (threadIdx.x == 0) {
            float ts = 0.0f; int tv = 0;
#pragma unroll
            for (int wi = 0; wi < NWARPS; wi++) { ts += f_sum[wi]; tv += f_cnt[wi]; }
            out[0] = ts / (float)max(tv, 1);
            g_count = 0;
        }
    }
}

extern "C" void kernel_launch(void* const* d_in, const int* in_sizes, int n_in,
                              void* d_out, int out_size)
{
    const float*  wl       = (const float*)d_in[0];
    const float*  Ry       = (const float*)d_in[1];
    const float4* points4  = (const float4*)d_in[2];
    const float2* density2 = (const float2*)d_in[3];
    const float*  center   = (const float*)d_in[4];
    float* out = (float*)d_out;

    wdm3d_fused_kernel<<<NBLOCKS, NTHREADS>>>(wl, Ry, points4, density2, center, out);
}

// round 9
// speedup vs baseline: 1.1484x; 1.0755x over previous
#include <cuda_runtime.h>
#include <math_constants.h>

#define N_BOX 1024
#define P_PTS 4096
#define NTHREADS 256
#define NWARPS (NTHREADS / 32)
#define NBLOCKS N_BOX                        /* SPLIT = 1 */
#define VEC_PER_BLK (P_PTS / 2)              /* 2048 float4 per box */
#define ITERS (VEC_PER_BLK / NTHREADS)       /* 8 */
#define STAGE 4                              /* vecs per stage (2 stages) */

#define PI_F      3.14159274101257324219f
#define HALF_PI_F 1.57079637050628662109f

__device__ float g_psum[NBLOCKS];
__device__ int   g_pcnt[NBLOCKS];
__device__ int   g_count;   // zero-init at load; reset by last block each launch

__device__ __forceinline__ float frcp_approx(float x) {
    float r;
    asm("rcp.approx.f32 %0, %1;" : "=f"(r) : "f"(x));
    return r;
}

// branchless: ix-space open interval (lo,hi) on ix = bs*u -> u-space |u-MID|<HW
__device__ __forceinline__ void make_interval(float lo, float hi, float bs, float rb,
                                              float& MID, float& HW)
{
    const float a = lo * rb, b = hi * rb;
    const float A = fminf(a, b), B = fmaxf(a, b);
    MID = 0.5f * (A + B);
    HW  = 0.5f * (B - A);
    if (bs == 0.0f) {               // ix==0 always: inside iff 0 in (lo,hi)
        MID = 0.0f;
        HW  = (lo < 0.0f && hi > 0.0f) ? CUDART_INF_F : -1.0f;
    }
    if (lo >= hi) { MID = 0.0f; HW = -1.0f; }   // empty (degenerate edge)
}

__global__ __launch_bounds__(NTHREADS, 4)
void wdm3d_fused_kernel(const float*  __restrict__ wl,
                        const float*  __restrict__ Ry,
                        const float4* __restrict__ points4,
                        const float2* __restrict__ density2,
                        const float*  __restrict__ center,
                        float* __restrict__ out)
{
    const int n = blockIdx.x;                 // box index
    const unsigned full = 0xFFFFFFFFu;

    const size_t basev = (size_t)n * VEC_PER_BLK;
    const float4* __restrict__ pts = points4  + basev;
    const float2* __restrict__ den = density2 + basev;

    // ---------------- stage-A loads first: DRAM latency overlaps preamble
    float4 pA[STAGE];
    float2 dA[STAGE];
#pragma unroll
    for (int it = 0; it < STAGE; it++) {
        pA[it] = pts[threadIdx.x + it * NTHREADS];
        dA[it] = den[threadIdx.x + it * NTHREADS];
    }

    // ---------------- per-box constants (block-uniform, warp-redundant, no barrier)
    float k1, k2, bsA, bsB, bsC, bsD;
    float MX0, WX0, MY0, WY0, MX1, WX1, MY1, WY1;
    float MX2, WX2, MY2, WY2, MX3, WX3, MY3, WY3;
    {
        const float w  = __ldg(&wl[2 * n]);
        const float l  = __ldg(&wl[2 * n + 1]);
        const float ry = __ldg(&Ry[n]);
        const float ccx = __ldg(&center[2 * n]);
        const float ccy = __ldg(&center[2 * n + 1]);

        // len*cos(init_theta±ry) collapse to linear forms in (w,l,sincos(ry))
        float sr, cr;
        sincosf(ry, &sr, &cr);
        const float P  = 0.5f * (l * cr - w * sr);
        const float Q  = 0.5f * (w * cr + l * sr);
        const float R  = 0.5f * (l * cr + w * sr);
        const float S_ = 0.5f * (w * cr - l * sr);

        const float cx0 = ccx + P,  cy0 = ccy + Q;
        const float cx1 = ccx - R,  cy1 = ccy + S_;
        const float cx2 = ccx - P,  cy2 = ccy - Q;
        const float cx3 = ccx + R,  cy3 = ccy - S_;

        float ry2 = (ry == HALF_PI_F) ? (ry - 0.0001f) : ry;
        ry2 = (ry2 == 0.0f) ? (ry2 + 0.0001f) : ry2;
        float sr2 = sr, cr2 = cr;
        if (ry2 != ry) sincosf(ry2, &sr2, &cr2);
        k1 =  sr2 * frcp_approx(cr2);      // tan(ry2)
        k2 = -cr2 * frcp_approx(sr2);      // tan(ry2+pi/2)

        float bs[4];
        bs[0] = cy0 - k1 * cx0;   // b11
        bs[1] = cy2 - k2 * cx2;   // b22
        bs[2] = cy2 - k1 * cx2;   // b12
        bs[3] = cy0 - k2 * cx0;   // b21

        const float cxr[4] = { rintf(cx0 * 1e4f), rintf(cx1 * 1e4f),
                               rintf(cx2 * 1e4f), rintf(cx3 * 1e4f) };
        const float cyr[4] = { rintf(cy0 * 1e4f), rintf(cy1 * 1e4f),
                               rintf(cy2 * 1e4f), rintf(cy3 * 1e4f) };

        float MX[4], WX[4], MY[4], WY[4];
        const float S = 1e-4f;
#pragma unroll
        for (int e = 0; e < 4; e++) {
            const int e2 = (e + 1) & 3;
            const float rb  = frcp_approx(bs[e]);     // shared by X & Y intervals
            const float lox = (fminf(cxr[e], cxr[e2]) + 0.5f) * S;
            const float hix = (fmaxf(cxr[e], cxr[e2]) - 0.5f) * S;
            const float loy = (fminf(cyr[e], cyr[e2]) + 0.5f) * S;
            const float hiy = (fmaxf(cyr[e], cyr[e2]) - 0.5f) * S;
            make_interval(lox, hix, bs[e], rb, MX[e], WX[e]);
            make_interval(loy, hiy, bs[e], rb, MY[e], WY[e]);
        }

        int p0 = 0, p2 = 2;
        if (fabsf(bs[2]) < fabsf(bs[0])) { p0 = 2; p2 = 0; }
        int p1 = 1, p3 = 3;
        if (fabsf(bs[3]) < fabsf(bs[1])) { p1 = 3; p3 = 1; }

        bsA = bs[p0]; bsB = bs[p2];
        bsC = bs[p1]; bsD = bs[p3];
        MX0 = MX[p0]; WX0 = WX[p0]; MY0 = MY[p0]; WY0 = WY[p0];
        MX1 = MX[p2]; WX1 = WX[p2]; MY1 = MY[p2]; WY1 = WY[p2];
        MX2 = MX[p1]; WX2 = WX[p1]; MY2 = MY[p1]; WY2 = WY[p1];
        MX3 = MX[p3]; WX3 = WX[p3]; MY3 = MY[p3]; WY3 = WY[p3];
    }

    float sum = 0.0f;
    int   cnt = 0;

#define PROCESS_POINT(PX_, PY_, DENS_)                                          \
    do {                                                                        \
        const float px = ((PX_) == 0.0f) ? 0.0001f : (PX_);                     \
        const float py = (PY_);                                                 \
        const float r1 = frcp_approx(fmaf(-k1, px, py));                        \
        const float r2 = frcp_approx(fmaf(-k2, px, py));                        \
        const float u1 = px * r1, v1 = py * r1;                                 \
        const float u2 = px * r2, v2 = py * r2;                                 \
        const bool mA = (fabsf(u1 - MX0) < WX0) || (fabsf(v1 - MY0) < WY0);     \
        const bool mB = (fabsf(u1 - MX1) < WX1) || (fabsf(v1 - MY1) < WY1);     \
        const bool mC = (fabsf(u2 - MX2) < WX2) || (fabsf(v2 - MY2) < WY2);     \
        const bool mD = (fabsf(u2 - MX3) < WX3) || (fabsf(v2 - MY3) < WY3);     \
        /* exactly-2-of-4: parity==0 AND any AND !all (counts 0,2,4 share    */ \
        /* parity 0; exclude 0 via any, 4 via !all)                          */ \
        const bool par = (mA ^ mB) ^ (mC ^ mD);                                 \
        const bool any = (mA | mB) | (mC | mD);                                 \
        const bool all = (mA & mB) & (mC & mD);                                 \
        /* g = bs*r; cen ∝ |px|*|g| -> argmin compares |g|;                  */ \
        /* dis = (|px|+|py|)*|g-1|                                           */ \
        const float g02 = (mA ? bsA : bsB) * r1;                                \
        const float g13 = (mC ? bsC : bsD) * r2;                                \
        const float c02 = (mA | mB) ? fabsf(g02) : CUDART_INF_F;                \
        const float c13 = (mC | mD) ? fabsf(g13) : CUDART_INF_F;                \
        const float gw  = (c02 <= c13) ? g02 : g13;                             \
        if (!par & any & !all) {                                                \
            const float dsel = (fabsf(px) + fabsf(py)) * fabsf(gw - 1.0f);      \
            sum += dsel * frcp_approx(DENS_);                                   \
            cnt += 1;                                                           \
        }                                                                       \
    } while (0)

    // stage A
#pragma unroll
    for (int it = 0; it < STAGE; it++) {
        PROCESS_POINT(pA[it].x, pA[it].y, dA[it].x);
        PROCESS_POINT(pA[it].z, pA[it].w, dA[it].y);
    }

    // stage B (loads issued after stage-A compute; hidden by resident warps)
    float4 pB[STAGE];
    float2 dB[STAGE];
#pragma unroll
    for (int it = 0; it < STAGE; it++) {
        pB[it] = pts[threadIdx.x + (STAGE + it) * NTHREADS];
        dB[it] = den[threadIdx.x + (STAGE + it) * NTHREADS];
    }
#pragma unroll
    for (int it = 0; it < STAGE; it++) {
        PROCESS_POINT(pB[it].x, pB[it].y, dB[it].x);
        PROCESS_POINT(pB[it].z, pB[it].w, dB[it].y);
    }

    // ---------------- block reduction
#pragma unroll
    for (int off = 16; off > 0; off >>= 1) {
        sum += __shfl_down_sync(full, sum, off);
        cnt += __shfl_down_sync(full, cnt, off);
    }

    __shared__ float s_sum[NWARPS];
    __shared__ int   s_cnt[NWARPS];
    __shared__ bool  s_last;
    const int warp = threadIdx.x >> 5;
    const int lane = threadIdx.x & 31;
    if (lane == 0) { s_sum[warp] = sum; s_cnt[warp] = cnt; }
    __syncthreads();

    if (threadIdx.x == 0) {
        float fs = 0.0f; int fc = 0;
#pragma unroll
        for (int wi = 0; wi < NWARPS; wi++) { fs += s_sum[wi]; fc += s_cnt[wi]; }
        g_psum[n] = fs;
        g_pcnt[n] = fc;
        __threadfence();
        const int prev = atomicAdd(&g_count, 1);
        s_last = (prev == gridDim.x - 1);
    }
    __syncthreads();

    // ---------------- last block: deterministic final reduction over boxes
    if (s_last) {
        float fs = 0.0f;
        int   fv = 0;
#pragma unroll
        for (int jb = 0; jb < N_BOX / NTHREADS; jb++) {
            const int b = threadIdx.x + jb * NTHREADS;
            const float bsum = __ldcg(&g_psum[b]);
            const int   bcnt = __ldcg(&g_pcnt[b]);
            const bool valid = (bcnt >= 3);
            fs += valid ? (bsum / (float)max(bcnt, 1)) : 0.0f;
            fv += valid ? 1 : 0;
        }
#pragma unroll
        for (int off = 16; off > 0; off >>= 1) {
            fs += __shfl_down_sync(full, fs, off);
            fv += __shfl_down_sync(full, fv, off);
        }
        __shared__ float f_sum[NWARPS];
        __shared__ int   f_cnt[NWARPS];
        if (lane == 0) { f_sum[warp] = fs; f_cnt[warp] = fv; }
        __syncthreads();
        if (threadIdx.x == 0) {
            float ts = 0.0f; int tv = 0;
#pragma unroll
            for (int wi = 0; wi < NWARPS; wi++) { ts += f_sum[wi]; tv += f_cnt[wi]; }
            out[0] = ts / (float)max(tv, 1);
            g_count = 0;
        }
    }
}

extern "C" void kernel_launch(void* const* d_in, const int* in_sizes, int n_in,
                              void* d_out, int out_size)
{
    const float*  wl       = (const float*)d_in[0];
    const float*  Ry       = (const float*)d_in[1];
    const float4* points4  = (const float4*)d_in[2];
    const float2* density2 = (const float2*)d_in[3];
    const float*  center   = (const float*)d_in[4];
    float* out = (float*)d_out;

    wdm3d_fused_kernel<<<NBLOCKS, NTHREADS>>>(wl, Ry, points4, density2, center, out);
}

// round 10
// speedup vs baseline: 1.4514x; 1.2639x over previous
#include <cuda_runtime.h>
#include <math_constants.h>

#define N_BOX 1024
#define P_PTS 4096
#define NTHREADS 256
#define NWARPS (NTHREADS / 32)
#define NBLOCKS N_BOX                        /* SPLIT = 1 */
#define VEC_PER_BLK (P_PTS / 2)              /* 2048 float4 per box */
#define STAGE 4                              /* vecs per stage (2 stages, 16 pts/thread) */

#define PI_F      3.14159274101257324219f
#define HALF_PI_F 1.57079637050628662109f

__device__ float g_psum[NBLOCKS];
__device__ int   g_pcnt[NBLOCKS];
__device__ int   g_count;   // zero-init at load; reset by last block each launch

__device__ __forceinline__ float frcp_approx(float x) {
    float r;
    asm("rcp.approx.f32 %0, %1;" : "=f"(r) : "f"(x));
    return r;
}

__global__ __launch_bounds__(NTHREADS, 4)
void wdm3d_fused_kernel(const float*  __restrict__ wl,
                        const float*  __restrict__ Ry,
                        const float4* __restrict__ points4,
                        const float2* __restrict__ density2,
                        const float*  __restrict__ center,
                        float* __restrict__ out)
{
    const int n = blockIdx.x;                 // box index
    const unsigned full = 0xFFFFFFFFu;

    const size_t basev = (size_t)n * VEC_PER_BLK;
    const float4* __restrict__ pts = points4  + basev;
    const float2* __restrict__ den = density2 + basev;

    // ---------------- stage-A loads first: DRAM latency overlaps preamble
    float4 pA[STAGE];
    float2 dA[STAGE];
#pragma unroll
    for (int it = 0; it < STAGE; it++) {
        pA[it] = pts[threadIdx.x + it * NTHREADS];
        dA[it] = den[threadIdx.x + it * NTHREADS];
    }

    // ---------------- per-box constants: slab model, 6 floats total
    // Box frame: u-axis = x rotated by Ry. Line L(t) = t*(px,py).
    //   qu(t) = t*au - cu with au = px*cr + py*sr, cu = ccx*cr + ccy*sr
    //   qv(t) = t*av - cv with av = py*cr - px*sr, cv = ccy*cr - ccx*sr
    // Box interior: |qu| < l/2, |qv| < w/2.
    // Edge-line crossings: t = (cu ± l/2)/au, (cv ± w/2)/av.
    // mask-count==2  <=>  slab overlap  tE < tX  (open, matches open intervals)
    // cen = |t|*||p||  ->  argmin by |t|;  dis = |t-1| * (|px|+|py|)
    float cr, sr, Cu0, Cu1, Cv0, Cv1;
    {
        const float w   = __ldg(&wl[2 * n]);
        const float l   = __ldg(&wl[2 * n + 1]);
        const float ry  = __ldg(&Ry[n]);
        const float ccx = __ldg(&center[2 * n]);
        const float ccy = __ldg(&center[2 * n + 1]);

        sincosf(ry, &sr, &cr);
        const float cu = ccx * cr + ccy * sr;
        const float cv = ccy * cr - ccx * sr;
        const float hl = 0.5f * l;
        const float hw = 0.5f * w;
        Cu0 = cu - hl; Cu1 = cu + hl;
        Cv0 = cv - hw; Cv1 = cv + hw;
    }

    float sum = 0.0f;
    int   cnt = 0;

#define PROCESS_POINT(PX_, PY_, DENS_)                                          \
    do {                                                                        \
        const float px = ((PX_) == 0.0f) ? 0.0001f : (PX_);                     \
        const float py = (PY_);                                                 \
        const float au = fmaf(px, cr, py * sr);                                 \
        const float av = fmaf(py, cr, -px * sr);                                \
        const float ru = frcp_approx(au);                                       \
        const float rv = frcp_approx(av);                                       \
        const float a0 = Cu0 * ru, a1 = Cu1 * ru;                               \
        const float b0 = Cv0 * rv, b1 = Cv1 * rv;                               \
        const float tE = fmaxf(fminf(a0, a1), fminf(b0, b1));                   \
        const float tX = fminf(fmaxf(a0, a1), fmaxf(b0, b1));                   \
        const bool hit = tE < tX;                                               \
        const float tsel = (fabsf(tE) <= fabsf(tX)) ? tE : tX;                  \
        if (hit) {                                                              \
            const float dsel = (fabsf(px) + fabsf(py)) * fabsf(tsel - 1.0f);    \
            sum += dsel * frcp_approx(DENS_);                                   \
            cnt += 1;                                                           \
        }                                                                       \
    } while (0)

    // stage A
#pragma unroll
    for (int it = 0; it < STAGE; it++) {
        PROCESS_POINT(pA[it].x, pA[it].y, dA[it].x);
        PROCESS_POINT(pA[it].z, pA[it].w, dA[it].y);
    }

    // stage B
    float4 pB[STAGE];
    float2 dB[STAGE];
#pragma unroll
    for (int it = 0; it < STAGE; it++) {
        pB[it] = pts[threadIdx.x + (STAGE + it) * NTHREADS];
        dB[it] = den[threadIdx.x + (STAGE + it) * NTHREADS];
    }
#pragma unroll
    for (int it = 0; it < STAGE; it++) {
        PROCESS_POINT(pB[it].x, pB[it].y, dB[it].x);
        PROCESS_POINT(pB[it].z, pB[it].w, dB[it].y);
    }

    // ---------------- block reduction
#pragma unroll
    for (int off = 16; off > 0; off >>= 1) {
        sum += __shfl_down_sync(full, sum, off);
        cnt += __shfl_down_sync(full, cnt, off);
    }

    __shared__ float s_sum[NWARPS];
    __shared__ int   s_cnt[NWARPS];
    __shared__ bool  s_last;
    const int warp = threadIdx.x >> 5;
    const int lane = threadIdx.x & 31;
    if (lane == 0) { s_sum[warp] = sum; s_cnt[warp] = cnt; }
    __syncthreads();

    if (threadIdx.x == 0) {
        float fs = 0.0f; int fc = 0;
#pragma unroll
        for (int wi = 0; wi < NWARPS; wi++) { fs += s_sum[wi]; fc += s_cnt[wi]; }
        g_psum[n] = fs;
        g_pcnt[n] = fc;
        __threadfence();
        const int prev = atomicAdd(&g_count, 1);
        s_last = (prev == gridDim.x - 1);
    }
    __syncthreads();

    // ---------------- last block: deterministic final reduction over boxes
    if (s_last) {
        float fs = 0.0f;
        int   fv = 0;
#pragma unroll
        for (int jb = 0; jb < N_BOX / NTHREADS; jb++) {
            const int b = threadIdx.x + jb * NTHREADS;
            const float bsum = __ldcg(&g_psum[b]);
            const int   bcnt = __ldcg(&g_pcnt[b]);
            const bool valid = (bcnt >= 3);
            fs += valid ? (bsum / (float)max(bcnt, 1)) : 0.0f;
            fv += valid ? 1 : 0;
        }
#pragma unroll
        for (int off = 16; off > 0; off >>= 1) {
            fs += __shfl_down_sync(full, fs, off);
            fv += __shfl_down_sync(full, fv, off);
        }
        __shared__ float f_sum[NWARPS];
        __shared__ int   f_cnt[NWARPS];
        if (lane == 0) { f_sum[warp] = fs; f_cnt[warp] = fv; }
        __syncthreads();
        if (threadIdx.x == 0) {
            float ts = 0.0f; int tv = 0;
#pragma unroll
            for (int wi = 0; wi < NWARPS; wi++) { ts += f_sum[wi]; tv += f_cnt[wi]; }
            out[0] = ts / (float)max(tv, 1);
            g_count = 0;
        }
    }
}

extern "C" void kernel_launch(void* const* d_in, const int* in_sizes, int n_in,
                              void* d_out, int out_size)
{
    const float*  wl       = (const float*)d_in[0];
    const float*  Ry       = (const float*)d_in[1];
    const float4* points4  = (const float4*)d_in[2];
    const float2* density2 = (const float2*)d_in[3];
    const float*  center   = (const float*)d_in[4];
    float* out = (float*)d_out;

    wdm3d_fused_kernel<<<NBLOCKS, NTHREADS>>>(wl, Ry, points4, density2, center, out);
}

// round 11
// speedup vs baseline: 1.5863x; 1.0930x over previous
#include <cuda_runtime.h>
#include <math_constants.h>

#define N_BOX 1024
#define P_PTS 4096
#define NTHREADS 256
#define NWARPS (NTHREADS / 32)
#define SPLIT 2
#define NBLOCKS (N_BOX * SPLIT)              /* 2048 */
#define VEC_PER_BLK (P_PTS / 2 / SPLIT)      /* 1024 float4 per block */
#define ITERS (VEC_PER_BLK / NTHREADS)       /* 4 -> 8 pts/thread */

#define PI_F      3.14159274101257324219f
#define HALF_PI_F 1.57079637050628662109f

__device__ float g_psum[NBLOCKS];
__device__ int   g_pcnt[NBLOCKS];
__device__ int   g_count;   // zero-init at load; reset by last block each launch

__device__ __forceinline__ float frcp_approx(float x) {
    float r;
    asm("rcp.approx.f32 %0, %1;" : "=f"(r) : "f"(x));
    return r;
}

__global__ __launch_bounds__(NTHREADS, 6)
void wdm3d_fused_kernel(const float*  __restrict__ wl,
                        const float*  __restrict__ Ry,
                        const float4* __restrict__ points4,
                        const float2* __restrict__ density2,
                        const float*  __restrict__ center,
                        float* __restrict__ out)
{
    const int blk  = blockIdx.x;
    const int n    = blk >> 1;        // box index
    const int part = blk & 1;         // half of the point set
    const unsigned full = 0xFFFFFFFFu;

    const size_t basev = (size_t)n * (P_PTS / 2) + (size_t)part * VEC_PER_BLK;
    const float4* __restrict__ pts = points4  + basev;
    const float2* __restrict__ den = density2 + basev;

    // ---------------- ALL loads front-batched: max MLP, latency overlaps preamble
    float4 p[ITERS];
    float2 d[ITERS];
#pragma unroll
    for (int it = 0; it < ITERS; it++) {
        p[it] = pts[threadIdx.x + it * NTHREADS];
        d[it] = den[threadIdx.x + it * NTHREADS];
    }

    // ---------------- per-box constants: slab model, 6 floats total
    // Box frame: u-axis = x rotated by Ry. Line L(t) = t*(px,py).
    //   qu(t) = t*au - cu, au = px*cr + py*sr, cu = ccx*cr + ccy*sr
    //   qv(t) = t*av - cv, av = py*cr - px*sr, cv = ccy*cr - ccx*sr
    // Edge crossings: t = (cu ± l/2)/au, (cv ± w/2)/av.
    // mask-count==2 <=> slab overlap tE < tX (open)
    // cen = |t|*||p|| -> argmin by |t|;  dis = |t-1| * (|px|+|py|)
    float cr, sr, Cu0, Cu1, Cv0, Cv1;
    {
        const float w   = __ldg(&wl[2 * n]);
        const float l   = __ldg(&wl[2 * n + 1]);
        const float ry  = __ldg(&Ry[n]);
        const float ccx = __ldg(&center[2 * n]);
        const float ccy = __ldg(&center[2 * n + 1]);

        sincosf(ry, &sr, &cr);
        const float cu = ccx * cr + ccy * sr;
        const float cv = ccy * cr - ccx * sr;
        const float hl = 0.5f * l;
        const float hw = 0.5f * w;
        Cu0 = cu - hl; Cu1 = cu + hl;
        Cv0 = cv - hw; Cv1 = cv + hw;
    }

    float sum = 0.0f;
    int   cnt = 0;

#define PROCESS_POINT(PX_, PY_, DENS_)                                          \
    do {                                                                        \
        const float px = ((PX_) == 0.0f) ? 0.0001f : (PX_);                     \
        const float py = (PY_);                                                 \
        const float au = fmaf(px, cr, py * sr);                                 \
        const float av = fmaf(py, cr, -px * sr);                                \
        const float ru = frcp_approx(au);                                       \
        const float rv = frcp_approx(av);                                       \
        const float a0 = Cu0 * ru, a1 = Cu1 * ru;                               \
        const float b0 = Cv0 * rv, b1 = Cv1 * rv;                               \
        const float tE = fmaxf(fminf(a0, a1), fminf(b0, b1));                   \
        const float tX = fminf(fmaxf(a0, a1), fmaxf(b0, b1));                   \
        const bool hit = tE < tX;                                               \
        const float tsel = (fabsf(tE) <= fabsf(tX)) ? tE : tX;                  \
        if (hit) {                                                              \
            const float dsel = (fabsf(px) + fabsf(py)) * fabsf(tsel - 1.0f);    \
            sum += dsel * frcp_approx(DENS_);                                   \
            cnt += 1;                                                           \
        }                                                                       \
    } while (0)

#pragma unroll
    for (int it = 0; it < ITERS; it++) {
        PROCESS_POINT(p[it].x, p[it].y, d[it].x);
        PROCESS_POINT(p[it].z, p[it].w, d[it].y);
    }

    // ---------------- block reduction
#pragma unroll
    for (int off = 16; off > 0; off >>= 1) {
        sum += __shfl_down_sync(full, sum, off);
        cnt += __shfl_down_sync(full, cnt, off);
    }

    __shared__ float s_sum[NWARPS];
    __shared__ int   s_cnt[NWARPS];
    __shared__ bool  s_last;
    const int warp = threadIdx.x >> 5;
    const int lane = threadIdx.x & 31;
    if (lane == 0) { s_sum[warp] = sum; s_cnt[warp] = cnt; }
    __syncthreads();

    if (threadIdx.x == 0) {
        float fs = 0.0f; int fc = 0;
#pragma unroll
        for (int wi = 0; wi < NWARPS; wi++) { fs += s_sum[wi]; fc += s_cnt[wi]; }
        g_psum[blk] = fs;
        g_pcnt[blk] = fc;
        __threadfence();
        const int prev = atomicAdd(&g_count, 1);
        s_last = (prev == gridDim.x - 1);
    }
    __syncthreads();

    // ---------------- last block: deterministic final reduction over boxes
    if (s_last) {
        float fs = 0.0f;
        int   fv = 0;
#pragma unroll
        for (int jb = 0; jb < N_BOX / NTHREADS; jb++) {
            const int b = threadIdx.x + jb * NTHREADS;
            float bsum = 0.0f; int bcnt = 0;
#pragma unroll
            for (int q = 0; q < SPLIT; q++) {
                bsum += __ldcg(&g_psum[SPLIT * b + q]);
                bcnt += __ldcg(&g_pcnt[SPLIT * b + q]);
            }
            const bool valid = (bcnt >= 3);
            fs += valid ? (bsum / (float)max(bcnt, 1)) : 0.0f;
            fv += valid ? 1 : 0;
        }
#pragma unroll
        for (int off = 16; off > 0; off >>= 1) {
            fs += __shfl_down_sync(full, fs, off);
            fv += __shfl_down_sync(full, fv, off);
        }
        __shared__ float f_sum[NWARPS];
        __shared__ int   f_cnt[NWARPS];
        if (lane == 0) { f_sum[warp] = fs; f_cnt[warp] = fv; }
        __syncthreads();
        if (threadIdx.x == 0) {
            float ts = 0.0f; int tv = 0;
#pragma unroll
            for (int wi = 0; wi < NWARPS; wi++) { ts += f_sum[wi]; tv += f_cnt[wi]; }
            out[0] = ts / (float)max(tv, 1);
            g_count = 0;
        }
    }
}

extern "C" void kernel_launch(void* const* d_in, const int* in_sizes, int n_in,
                              void* d_out, int out_size)
{
    const float*  wl       = (const float*)d_in[0];
    const float*  Ry       = (const float*)d_in[1];
    const float4* points4  = (const float4*)d_in[2];
    const float2* density2 = (const float2*)d_in[3];
    const float*  center   = (const float*)d_in[4];
    float* out = (float*)d_out;

    wdm3d_fused_kernel<<<NBLOCKS, NTHREADS>>>(wl, Ry, points4, density2, center, out);
}